// round 17
// baseline (speedup 1.0000x reference)
#include <cuda_runtime.h>
#include <cuda_fp16.h>
#include <cstdint>

// ---------------------------------------------------------------------------
// SelfAttention B=4,T=2048,D=1024 fp32 causal — Round 16.
// Pure fp16 GEMMs (fp32 accum). R16: 256-thread CTAs, 8 warps (2m x 4n grid
// of 64x32 warp tiles) -> 4 warps/SMSP (was 2) at same RF budget; fragment
// redundancy rises but crossbar has 2x headroom (recalibrated ~256B/cyc).
// Conflict-free 128B-row (r&7)-rotation swizzle, triple buffer, 1 barrier/it,
// stage(i+2) prefetched before compute.
// ---------------------------------------------------------------------------

#define BUFB 32768u             // per buffer: A(16KB) + B(16KB), 128B rows
#define SMEM_TOT (3 * 32768)    // triple buffered = 96KB/CTA

// ---- global scratch (no cudaMalloc allowed) ----
__device__ unsigned g_e16[4UL * 2048 * 1024];       // E = exp(S/32) fp16 pairs
__device__ unsigned g_xhi[8192 * 512];
__device__ unsigned g_wthi[3 * 1024 * 512];         // W^T packed, contiguous
__device__ unsigned g_qkvhi[3 * 8192 * 512];        // q,k,v packed
__device__ unsigned g_vthi[4 * 1024 * 1024];        // V^T packed along tok
__device__ float    g_bias[3072];

__device__ __forceinline__ uint32_t smem_u32(const void* p) {
    uint32_t a;
    asm("{ .reg .u64 t; cvta.to.shared.u64 t, %1; cvt.u32.u64 %0, t; }"
        : "=r"(a) : "l"(p));
    return a;
}
__device__ __forceinline__ void cp16(uint32_t dst, const void* src) {
    asm volatile("cp.async.cg.shared.global [%0], [%1], 16;" :: "r"(dst), "l"(src));
}
__device__ __forceinline__ void cp_commit() {
    asm volatile("cp.async.commit_group;" ::: "memory");
}
__device__ __forceinline__ void ldm4(unsigned* r, uint32_t addr) {
    asm volatile("ldmatrix.sync.aligned.m8n8.x4.shared.b16 {%0,%1,%2,%3}, [%4];"
                 : "=r"(r[0]), "=r"(r[1]), "=r"(r[2]), "=r"(r[3]) : "r"(addr));
}
__device__ __forceinline__ void mma_f16(float* c, const unsigned* a, const unsigned* b)
{
    asm volatile(
        "mma.sync.aligned.m16n8k16.row.col.f32.f16.f16.f32 "
        "{%0,%1,%2,%3}, {%4,%5,%6,%7}, {%8,%9}, {%0,%1,%2,%3};\n"
        : "+f"(c[0]), "+f"(c[1]), "+f"(c[2]), "+f"(c[3])
        : "r"(a[0]), "r"(a[1]), "r"(a[2]), "r"(a[3]), "r"(b[0]), "r"(b[1]));
}
__device__ __forceinline__ unsigned pack_hi(float f0, float f1) {
    __half2 hh = __floats2half2_rn(f0, f1);
    return *(unsigned*)&hh;
}
__device__ __forceinline__ float sum2(unsigned w) {
    float2 f = __half22float2(*(__half2*)&w);
    return f.x + f.y;
}

// ---------------- unified NT GEMM: D[128,128] = A[m0:,:K] B[n0:,:K]^T ------
// 8 warps, 64x32 warp tiles (2m x 4n). Smem rows: 128B (64 k per stage);
// chunk c (16B) of row r at r*128 + ((c + (r&7))&7)*16 (conflict-free).
// MODE 0: +bias[globalcol] -> packed out, matrix-split every 1024 cols.
// MODE 2: E = exp(acc*scale), causal mask, packed out (per-batch ohb offset).
// MODE 3: O = acc / rowsum(A) -> fp32 out (Z accumulated from A fragments).
template<int MODE, bool CAUSAL, bool KEND>
__global__ void __launch_bounds__(256, 2)
nt_gemm(const unsigned* __restrict__ Ahi_, int aw, long long ab,
        const unsigned* __restrict__ Bhi_, int bw, long long bb,
        int Ktot, const float* __restrict__ bias, float scale,
        float* __restrict__ outf, int ldo, long long ob,
        unsigned* __restrict__ ohi, int ow, long long ohb, int matstride)
{
    // heavy-first ordering for causal / k-truncated kernels (tail balance)
    const int by = (CAUSAL || KEND) ? ((int)gridDim.y - 1 - (int)blockIdx.y)
                                    : (int)blockIdx.y;
    const int m0 = by * 128, n0 = blockIdx.x * 128, bz = blockIdx.z;
    if (CAUSAL && n0 > m0 + 127) return;
    extern __shared__ unsigned sm[];
    const uint32_t sb = smem_u32(sm);
    const int tid = threadIdx.x;
    const int lane = tid & 31, warp = tid >> 5;
    const int gid = lane >> 2, tig = lane & 3;
    const int wm0 = (warp & 1) * 64, wn0 = (warp >> 1) * 32;

    const unsigned* Ahi = Ahi_ + (size_t)bz * ab;
    const unsigned* Bhi = Bhi_ + (size_t)bz * bb;

    const int kend = KEND ? (m0 + 128) : Ktot;
    const int niter = kend >> 6;          // 64 k (32 kpair words) per iter

    // per-lane fragment row bases + chunk rotation (rot invariant: 16 ≡ 0 mod 8)
    const int ra = wm0 + (lane & 15);
    const uint32_t a_row = sb + (uint32_t)ra * 128;
    const uint32_t ja = (uint32_t)((lane >> 4) + (ra & 7));
    const int rb = wn0 + ((lane >> 4) & 1) * 8 + (lane & 7);
    const uint32_t b_row = sb + 16384 + (uint32_t)rb * 128;
    const uint32_t jb = (uint32_t)(((lane >> 3) & 1) + (rb & 7));

    // stage 64-k tile 'it' into buffer bsel (one cp.async group); 256 threads
    auto stage = [&](int bsel, int it) {
        const uint32_t base = sb + (uint32_t)bsel * BUFB;
#pragma unroll
        for (int p = 0; p < 4; p++) {
            const int id = tid + p * 256;
            const int row = id >> 3, c = id & 7;
            const uint32_t so = (uint32_t)(row * 128 + (((c + (row & 7)) & 7) * 16));
            cp16(base + so,         Ahi + (size_t)(m0 + row) * aw + it * 32 + c * 4);
            cp16(base + 16384 + so, Bhi + (size_t)(n0 + row) * bw + it * 32 + c * 4);
        }
        cp_commit();
    };

    float acc[4][4][4] = {};
    float2 zacc[4] = {};   // MODE 3: row sums (r0, r0+8) per mi

    stage(0, 0);
    if (niter > 1) stage(1, 1);

    int bsel = 0;   // = i % 3
    for (int i = 0; i < niter; i++) {
        if (i + 1 < niter) asm volatile("cp.async.wait_group 1;" ::: "memory");
        else               asm volatile("cp.async.wait_group 0;" ::: "memory");
        __syncthreads();   // single barrier per 64-k iteration

        // prefetch i+2 right after barrier (buffer free since iter i-1)
        if (i + 2 < niter) {
            int b2 = bsel + 2; if (b2 >= 3) b2 -= 3;
            stage(b2, i + 2);
        }

        const uint32_t bufoff = (uint32_t)bsel * BUFB;
#pragma unroll
        for (int ks = 0; ks < 4; ks++) {
            const uint32_t ca = ((ks * 2 + ja) & 7) * 16;   // swizzled chunk, A
            const uint32_t cb = ((ks * 2 + jb) & 7) * 16;   // swizzled chunk, B
            unsigned ahi[4][4];
            ldm4(ahi[0], a_row + bufoff + ca);
            ldm4(ahi[1], a_row + bufoff + ca + 2048);
            ldm4(ahi[2], a_row + bufoff + ca + 4096);
            ldm4(ahi[3], a_row + bufoff + ca + 6144);
            if (MODE == 3) {
#pragma unroll
                for (int mi = 0; mi < 4; mi++) {
                    zacc[mi].x += sum2(ahi[mi][0]) + sum2(ahi[mi][2]);  // row r0
                    zacc[mi].y += sum2(ahi[mi][1]) + sum2(ahi[mi][3]);  // row r0+8
                }
            }
            unsigned bh[2][4];
            ldm4(bh[0], b_row + bufoff + cb);
            ldm4(bh[1], b_row + bufoff + cb + 2048);
#pragma unroll
            for (int j = 0; j < 2; j++)          // B x4-ldm j covers n8 tiles 2j, 2j+1
#pragma unroll
                for (int tm = 0; tm < 2; tm++)
#pragma unroll
                    for (int mi = 0; mi < 4; mi++)
                        mma_f16(acc[mi][j * 2 + tm], ahi[mi], &bh[j][tm * 2]);
        }
        bsel = (bsel == 2) ? 0 : bsel + 1;
    }

    // ---- epilogue ----
#pragma unroll
    for (int mi = 0; mi < 4; mi++) {
        const int r0 = m0 + wm0 + mi * 16 + gid;
        if (MODE == 0) {
#pragma unroll
            for (int ni = 0; ni < 4; ni++) {
                const int col = n0 + wn0 + ni * 8 + 2 * tig;
                const int mat = n0 >> 10;           // whole n-tile in one matrix
                const int cl = col & 1023;
                float* a4 = acc[mi][ni];
                unsigned* dst = ohi + (size_t)mat * matstride;
                const float b0 = bias[col], b1 = bias[col + 1];
                dst[(size_t)r0 * ow + (cl >> 1)]       = pack_hi(a4[0] + b0, a4[1] + b1);
                dst[(size_t)(r0 + 8) * ow + (cl >> 1)] = pack_hi(a4[2] + b0, a4[3] + b1);
            }
        } else if (MODE == 2) {
            unsigned* dst = ohi + (size_t)bz * ohb;
#pragma unroll
            for (int ni = 0; ni < 4; ni++) {
                const int col = n0 + wn0 + ni * 8 + 2 * tig;
                float* a4 = acc[mi][ni];
                float e0 = (col     <= r0    ) ? __expf(a4[0] * scale) : 0.f;
                float e1 = (col + 1 <= r0    ) ? __expf(a4[1] * scale) : 0.f;
                float e2 = (col     <= r0 + 8) ? __expf(a4[2] * scale) : 0.f;
                float e3 = (col + 1 <= r0 + 8) ? __expf(a4[3] * scale) : 0.f;
                dst[(size_t)r0 * ow + (col >> 1)]       = pack_hi(e0, e1);
                dst[(size_t)(r0 + 8) * ow + (col >> 1)] = pack_hi(e2, e3);
            }
        } else {
            // MODE 3: reduce Z over tig lanes, normalize
            float zl = zacc[mi].x, zh = zacc[mi].y;
            zl += __shfl_xor_sync(0xffffffffu, zl, 1);
            zl += __shfl_xor_sync(0xffffffffu, zl, 2);
            zh += __shfl_xor_sync(0xffffffffu, zh, 1);
            zh += __shfl_xor_sync(0xffffffffu, zh, 2);
            const float rz = 1.f / zl, rz8 = 1.f / zh;
            float* dst = outf + (size_t)bz * ob;
#pragma unroll
            for (int ni = 0; ni < 4; ni++) {
                const int col = n0 + wn0 + ni * 8 + 2 * tig;
                float* a4 = acc[mi][ni];
                *(float2*)(dst + (size_t)r0 * ldo + col) =
                    make_float2(a4[0] * rz, a4[1] * rz);
                *(float2*)(dst + (size_t)(r0 + 8) * ldo + col) =
                    make_float2(a4[2] * rz8, a4[3] * rz8);
            }
        }
    }
}

// ---------------- prep: fp32 pairs -> packed fp16 hi ------------------------
__global__ void __launch_bounds__(256)
pack_hi_k(const float2* __restrict__ src, unsigned* __restrict__ hi, int n)
{
    for (int i = blockIdx.x * 256 + threadIdx.x; i < n; i += gridDim.x * 256) {
        float2 v = src[i];
        hi[i] = pack_hi(v.x, v.y);
    }
}

// ---- bias concat: [bq|bk|bv] -> g_bias[3072] -------------------------------
__global__ void __launch_bounds__(256)
biascat(const float* __restrict__ bq, const float* __restrict__ bk,
        const float* __restrict__ bv, float* __restrict__ dst)
{
    int i = blockIdx.x * 256 + threadIdx.x;   // grid 12 x 256 = 3072
    const float* src = (i < 1024) ? bq : (i < 2048) ? bk : bv;
    dst[i] = src[i & 1023];
}

// ---- transpose+pack 3 weights: src[1024,1024] fp32 -> [1024][512] packed ---
__global__ void __launch_bounds__(256)
tpack3(const float* __restrict__ Wq, const float* __restrict__ Wk,
       const float* __restrict__ Wv, unsigned* __restrict__ hi)
{
    __shared__ float t[64][33];
    const int z = blockIdx.z;
    const float* src = (z == 0) ? Wq : (z == 1) ? Wk : Wv;
    hi += (size_t)z * 524288;
    const int mb = blockIdx.y * 64, nb = blockIdx.x * 32;
    const int tx = threadIdx.x, ty = threadIdx.y;   // (32, 8)
#pragma unroll
    for (int r = 0; r < 8; r++) {
        int m = ty + r * 8;
        t[m][tx] = src[(size_t)(mb + m) * 1024 + nb + tx];
    }
    __syncthreads();
#pragma unroll
    for (int r = 0; r < 4; r++) {
        int nn = ty + r * 8;
        hi[(size_t)(nb + nn) * 512 + (mb >> 1) + tx] = pack_hi(t[2 * tx][nn], t[2 * tx + 1][nn]);
    }
}

// ---- transpose packed-hi v: [2048 tok][512 dw] -> [1024 dim][1024 tw] ------
__global__ void __launch_bounds__(256)
tpack_h(const unsigned* __restrict__ src, unsigned* __restrict__ dst)
{
    __shared__ unsigned t[64][33];
    const int bz = blockIdx.z;
    src += (size_t)bz * 2048 * 512;
    dst += (size_t)bz * 1024 * 1024;
    const int tb = blockIdx.y * 64, wb = blockIdx.x * 32;   // 64 toks x 64 dims
    const int tx = threadIdx.x, ty = threadIdx.y;           // (32, 8)
#pragma unroll
    for (int r = 0; r < 8; r++) {
        int m = ty + r * 8;
        t[m][tx] = src[(size_t)(tb + m) * 512 + wb + tx];
    }
    __syncthreads();
#pragma unroll
    for (int r = 0; r < 8; r++) {
        const int dl = ty + r * 8;          // local dim 0..63
        const int w = dl >> 1, sel = dl & 1;
        unsigned a = t[2 * tx][w], b = t[2 * tx + 1][w];
        unsigned word = __byte_perm(a, b, sel ? 0x7632 : 0x5410);
        dst[(size_t)(wb * 2 + dl) * 1024 + (tb >> 1) + tx] = word;
    }
}

// ---------------------------------------------------------------------------
extern "C" void kernel_launch(void* const* d_in, const int* in_sizes, int n_in,
                              void* d_out, int out_size)
{
    const float* x  = (const float*)d_in[0];
    const float* Wq = (const float*)d_in[1];
    const float* bq = (const float*)d_in[2];
    const float* Wk = (const float*)d_in[3];
    const float* bk = (const float*)d_in[4];
    const float* Wv = (const float*)d_in[5];
    const float* bv = (const float*)d_in[6];
    float* out = (float*)d_out;

    unsigned *e16, *xhi, *wthi, *qkvhi, *vthi;
    float* bias;
    cudaGetSymbolAddress((void**)&e16, g_e16);
    cudaGetSymbolAddress((void**)&xhi, g_xhi);
    cudaGetSymbolAddress((void**)&wthi, g_wthi);
    cudaGetSymbolAddress((void**)&qkvhi, g_qkvhi);
    cudaGetSymbolAddress((void**)&vthi, g_vthi);
    cudaGetSymbolAddress((void**)&bias, g_bias);

    cudaFuncSetAttribute((const void*)nt_gemm<0, false, false>,
                         cudaFuncAttributeMaxDynamicSharedMemorySize, SMEM_TOT);
    cudaFuncSetAttribute((const void*)nt_gemm<2, true, false>,
                         cudaFuncAttributeMaxDynamicSharedMemorySize, SMEM_TOT);
    cudaFuncSetAttribute((const void*)nt_gemm<3, false, true>,
                         cudaFuncAttributeMaxDynamicSharedMemorySize, SMEM_TOT);

    const int MS = 8192 * 512;              // per-matrix stride in g_qkvhi
    unsigned* qhi = qkvhi;
    unsigned* khi = qkvhi + MS;
    unsigned* vhi = qkvhi + 2 * MS;

    // --- prep: bias concat; pack x; transpose+pack weights (one launch) ---
    biascat<<<12, 256>>>(bq, bk, bv, bias);
    pack_hi_k<<<4096, 256>>>((const float2*)x, xhi, 8192 * 512);
    tpack3<<<dim3(32, 16, 3), dim3(32, 8)>>>(Wq, Wk, Wv, wthi);

    // --- fused q/k/v projection: [8192,1024] x [1024,3072] ---
    nt_gemm<0, false, false><<<dim3(24, 64, 1), 256, SMEM_TOT>>>(
        xhi, 512, 0, wthi, 512, 0,
        1024, bias, 0.f, nullptr, 0, 0, qkvhi, 512, 0, MS);

    // --- V^T re-pack (packed-hi transpose, per batch) ---
    tpack_h<<<dim3(16, 32, 4), dim3(32, 8)>>>(vhi, vthi);

    // --- scores: E = exp((q k^T)/32) causal-masked fp16 (heavy rows first) ---
    nt_gemm<2, true, false><<<dim3(16, 16, 4), 256, SMEM_TOT>>>(
        qhi, 512, (long long)2048 * 512,
        khi, 512, (long long)2048 * 512,
        1024, nullptr, 1.0f / 32.0f, nullptr, 0, 0,
        e16, 1024, (long long)2048 * 1024, 0);

    // --- O = (E V) / rowsum(E)  (k truncated; heavy rows first) ---
    nt_gemm<3, false, true><<<dim3(8, 16, 4), 256, SMEM_TOT>>>(
        e16, 1024, (long long)2048 * 1024,
        vthi, 1024, (long long)1024 * 1024,
        2048, nullptr, 0.f, out, 1024, (long long)2048 * 1024,
        nullptr, 0, 0, 0);
}